// round 1
// baseline (speedup 1.0000x reference)
#include <cuda_runtime.h>

#define HID 400
#define SEQ 8192
#define DEPTH 32
#define ROW (DEPTH * HID)          // 12800 floats per timestep
#define TPB 256
#define NWARP (TPB / 32)

__global__ void __launch_bounds__(TPB, 8)
stack_kernel(const float* __restrict__ hid,
             const float* __restrict__ W,
             const float* __restrict__ b,
             const float* __restrict__ D,
             float* __restrict__ out)
{
    const int t = blockIdx.x;
    const float* h = hid + (size_t)t * HID;

    // 4 partial dot products: W row0, row1, row2, D
    float a0 = 0.f, a1 = 0.f, a2 = 0.f, ad = 0.f;
    for (int i = threadIdx.x; i < HID; i += TPB) {
        float x = h[i];
        a0 += x * W[i];
        a1 += x * W[HID + i];
        a2 += x * W[2 * HID + i];
        ad += x * D[i];
    }

    // warp reduce
    #pragma unroll
    for (int o = 16; o > 0; o >>= 1) {
        a0 += __shfl_down_sync(0xffffffffu, a0, o);
        a1 += __shfl_down_sync(0xffffffffu, a1, o);
        a2 += __shfl_down_sync(0xffffffffu, a2, o);
        ad += __shfl_down_sync(0xffffffffu, ad, o);
    }

    __shared__ float sm[4][NWARP];
    __shared__ float sval;
    const int lane = threadIdx.x & 31;
    const int w    = threadIdx.x >> 5;
    if (lane == 0) {
        sm[0][w] = a0; sm[1][w] = a1; sm[2][w] = a2; sm[3][w] = ad;
    }
    __syncthreads();

    if (threadIdx.x == 0) {
        float l0 = b[0], l1 = b[1], l2 = b[2], d = 0.f;
        #pragma unroll
        for (int i = 0; i < NWARP; i++) {
            l0 += sm[0][i]; l1 += sm[1][i]; l2 += sm[2][i]; d += sm[3][i];
        }
        float m  = fmaxf(l0, fmaxf(l1, l2));
        float e0 = __expf(l0 - m);
        float e1 = __expf(l1 - m);
        float e2 = __expf(l2 - m);
        float p  = e0 / (e0 + e1 + e2);
        float v  = 1.f / (1.f + __expf(-d));
        sval = p * v;
    }
    __syncthreads();

    const float s = sval;
    const float4 sv = make_float4(s, s, s, s);
    const float4 zv = make_float4(0.f, 0.f, 0.f, 0.f);

    // Contiguous 12800-float slab for this timestep: row 0 = s, rows 1..31 = 0
    float4* o = reinterpret_cast<float4*>(out + (size_t)t * ROW);
    #pragma unroll 4
    for (int i = threadIdx.x; i < ROW / 4; i += TPB) {
        o[i] = (i < HID / 4) ? sv : zv;
    }
}

extern "C" void kernel_launch(void* const* d_in, const int* in_sizes, int n_in,
                              void* d_out, int out_size)
{
    const float* hid = (const float*)d_in[0];   // (1, 8192, 400)
    const float* W   = (const float*)d_in[1];   // (3, 400)
    const float* b   = (const float*)d_in[2];   // (3,)
    const float* D   = (const float*)d_in[3];   // (1, 400)
    float* out = (float*)d_out;                 // (1, 8192, 32, 400)

    stack_kernel<<<SEQ, TPB>>>(hid, W, b, D, out);
}